// round 12
// baseline (speedup 1.0000x reference)
#include <cuda_runtime.h>
#include <cuda_bf16.h>
#include <cstdint>

// Resample2d (FlowNet2 bilinear warp), fixed shapes:
//   input1 [B=4, C=64, H=384, W=512] fp32
//   input2 [B=4, 2,    H=384, W=512] fp32  (dx, dy)
//   out    [B=4, C=64, H=384, W=512] fp32
//
// R10 = re-bench of R9 (container failure was infra, not a verdict).
// R8 structure with exactly one change: gather loads use __ldcg (L2-only,
// no L1 line allocation). Discriminates the L1 cost decomposition:
//   fill model   -> ~95-105us (line-fill mgmt was 1-2 of ~4 cyc/gather)
//   sector model -> ~125-135us (sector-return wavefronts dominate)

#define RS_B 4
#define RS_C 64
#define RS_H 384
#define RS_W 512
#define RS_HW (RS_H * RS_W)
#define RS_CHW (RS_C * RS_HW)

__global__ __launch_bounds__(256, 8) void resample2d_kernel(
    const float* __restrict__ in1,   // [B,C,H,W]
    const float* __restrict__ flow,  // [B,2,H,W]
    float* __restrict__ out)         // [B,C,H,W]
{
    const int t = blockIdx.x * 256 + threadIdx.x;   // pixel index h*W+w
    const int b = blockIdx.y;
    if (t >= RS_HW) return;

    const int w = t & (RS_W - 1);
    const int h = t >> 9;                            // W = 512 = 2^9

    const float* flowb = flow + b * 2 * RS_HW;
    const float dx = __ldcs(flowb + t);
    const float dy = __ldcs(flowb + RS_HW + t);

    const float xf = (float)w + dx;
    const float yf = (float)h + dy;
    const float x0 = floorf(xf);
    const float y0 = floorf(yf);
    const float alpha = xf - x0;
    const float beta  = yf - y0;

    const int x0i = (int)x0;
    const int y0i = (int)y0;
    const int xL = min(max(x0i,     0), RS_W - 1);
    const int xR = min(max(x0i + 1, 0), RS_W - 1);
    const int yT = min(max(y0i,     0), RS_H - 1);
    const int yB = min(max(y0i + 1, 0), RS_H - 1);

    const float wTR = alpha * (1.0f - beta);
    const float wBL = (1.0f - alpha) * beta;
    const float wBR = alpha * beta;
    const float wTL = 1.0f - wTR - wBL - wBR;

    // Four gather base addresses for channel 0; channel step = HW floats.
    const float* base = in1 + b * RS_CHW;
    const float* pTL = base + yT * RS_W + xL;
    const float* pTR = base + yT * RS_W + xR;
    const float* pBL = base + yB * RS_W + xL;
    const float* pBR = base + yB * RS_W + xR;
    float* outp = out + b * RS_CHW + t;

#pragma unroll 2
    for (int c = 0; c < RS_C; ++c) {
        const int o = c * RS_HW;
        const float vTL = __ldcg(pTL + o);
        const float vTR = __ldcg(pTR + o);
        const float vBL = __ldcg(pBL + o);
        const float vBR = __ldcg(pBR + o);
        __stcs(outp + o,
               fmaf(wTL, vTL,
               fmaf(wTR, vTR,
               fmaf(wBL, vBL,
                    wBR * vBR))));
    }
}

extern "C" void kernel_launch(void* const* d_in, const int* in_sizes, int n_in,
                              void* d_out, int out_size)
{
    const float* in1  = (const float*)d_in[0];
    const float* flow = (const float*)d_in[1];
    float* out = (float*)d_out;

    dim3 grid(RS_HW / 256, RS_B);   // 768 x 4 = 3072 blocks
    resample2d_kernel<<<grid, 256>>>(in1, flow, out);
}

// round 15
// speedup vs baseline: 1.7033x; 1.7033x over previous
#include <cuda_runtime.h>
#include <cuda_bf16.h>
#include <cstdint>

// Resample2d (FlowNet2 bilinear warp), fixed shapes:
//   input1 [B=4, C=64, H=384, W=512] fp32
//   input2 [B=4, 2,    H=384, W=512] fp32  (dx, dy)
//   out    [B=4, C=64, H=384, W=512] fp32
//
// R15 = same experiment as R13/R14 (both lost to container flakes), with the
// block mapping expressed via a 3D grid instead of packed blockIdx.x math.
// Block = 2 adjacent rows x 128 columns; warp = 32 consecutive columns of
// one row. Rows h and h+1 share an L1 so each input line is miss-filled
// ~once instead of ~twice (the .cg experiment proved L1 hit service is
// load-bearing; duplicate fills are the identified waste).
// Codegen otherwise identical to the 114us R1 baseline.

#define RS_B 4
#define RS_C 64
#define RS_H 384
#define RS_W 512
#define RS_HW (RS_H * RS_W)
#define RS_CHW (RS_C * RS_HW)

__global__ __launch_bounds__(256) void resample2d_kernel(
    const float* __restrict__ in1,   // [B,C,H,W]
    const float* __restrict__ flow,  // [B,2,H,W]
    float* __restrict__ out)         // [B,C,H,W]
{
    const int cx    = blockIdx.x;              // column chunk 0..3
    const int hpair = blockIdx.y;              // row pair 0..191
    const int b     = blockIdx.z;              // batch 0..3

    const int h   = hpair * 2 + (threadIdx.x >> 7);      // 2 rows per block
    const int col = cx * 128 + (threadIdx.x & 127);
    const int t   = h * RS_W + col;

    const float* flowb = flow + b * 2 * RS_HW;
    const float dx = flowb[t];
    const float dy = flowb[RS_HW + t];

    const float xf = (float)col + dx;
    const float yf = (float)h + dy;
    const float x0 = floorf(xf);
    const float y0 = floorf(yf);
    const float alpha = xf - x0;
    const float beta  = yf - y0;

    const int x0i = (int)x0;
    const int y0i = (int)y0;
    const int xL = min(max(x0i,     0), RS_W - 1);
    const int xR = min(max(x0i + 1, 0), RS_W - 1);
    const int yT = min(max(y0i,     0), RS_H - 1);
    const int yB = min(max(y0i + 1, 0), RS_H - 1);

    const float wTR = alpha * (1.0f - beta);
    const float wBL = (1.0f - alpha) * beta;
    const float wBR = alpha * beta;
    const float wTL = 1.0f - wTR - wBL - wBR;

    const int oTL = yT * RS_W + xL;
    const int oTR = yT * RS_W + xR;
    const int oBL = yB * RS_W + xL;
    const int oBR = yB * RS_W + xR;

    const float* base = in1 + b * RS_CHW;
    float* outp = out + b * RS_CHW + t;

#pragma unroll 4
    for (int c = 0; c < RS_C; ++c) {
        const float* p = base + c * RS_HW;
        const float vTL = __ldg(p + oTL);
        const float vTR = __ldg(p + oTR);
        const float vBL = __ldg(p + oBL);
        const float vBR = __ldg(p + oBR);
        outp[c * RS_HW] = fmaf(wTL, vTL,
                          fmaf(wTR, vTR,
                          fmaf(wBL, vBL,
                               wBR * vBR)));
    }
}

extern "C" void kernel_launch(void* const* d_in, const int* in_sizes, int n_in,
                              void* d_out, int out_size)
{
    const float* in1  = (const float*)d_in[0];
    const float* flow = (const float*)d_in[1];
    float* out = (float*)d_out;

    dim3 grid(RS_W / 128, RS_H / 2, RS_B);   // 4 x 192 x 4 = 3072 blocks
    resample2d_kernel<<<grid, 256>>>(in1, flow, out);
}